// round 6
// baseline (speedup 1.0000x reference)
#include <cuda_runtime.h>
#include <cstdint>

#define TT 2048
#define DD 512
#define STEPS 8
#define NBLK (TT / STEPS)   // 256
#define NSTG 3
#define TILE_R 32           // rows per CTA
#define STEP_F 128          // floats per step in a stage: r32 w32 k32 v32
#define STAGE_B (STEPS * STEP_F * 4)  // 4096 bytes per stage buffer
#define PPITCH 65           // part[] col pitch (floats): conflict-free R/W
#define NRB 16              // row blocks

// 16 row-blocks of partial y sums, [16][T][D] = 64 MB scratch
__device__ float g_part[(size_t)NRB * TT * DD];

typedef unsigned long long ull;

__device__ __forceinline__ ull pk2(float lo, float hi) {
    ull r; asm("mov.b64 %0,{%1,%2};" : "=l"(r) : "f"(lo), "f"(hi)); return r;
}
__device__ __forceinline__ void up2(ull x, float& lo, float& hi) {
    asm("mov.b64 {%0,%1},%2;" : "=f"(lo), "=f"(hi) : "l"(x));
}
__device__ __forceinline__ ull f2fma(ull a, ull b, ull c) {
    ull d; asm("fma.rn.f32x2 %0,%1,%2,%3;" : "=l"(d) : "l"(a), "l"(b), "l"(c)); return d;
}
__device__ __forceinline__ ull f2mul(ull a, ull b) {
    ull d; asm("mul.rn.f32x2 %0,%1,%2;" : "=l"(d) : "l"(a), "l"(b)); return d;
}

#define CP16(dst, src) asm volatile("cp.async.cg.shared.global [%0], [%1], 16;\n" :: "r"(dst), "l"(src))
#define CP_COMMIT()    asm volatile("cp.async.commit_group;\n")
#define CP_WAIT1()     asm volatile("cp.async.wait_group 1;\n" ::: "memory")

// ---------------------------------------------------------------------------
// Main recurrence kernel. Grid: (16 col-blocks, 16 row-blocks) = 256 CTAs,
// 2 CTAs/SM (16 warps/SM -> 4/SMSP for latency hiding).
// CTA tile: 32 rows x 32 cols. Warp wid owns cols [wid*4,wid*4+4), all 32
// rows; lane = rg*4 + c (rg 0..7 = 4-row groups). Thread: 4 rows x 1 col as
// 2 f32x2 pairs. One __syncthreads + one batched smem reduction per 8 steps.
// ---------------------------------------------------------------------------
__global__ void __launch_bounds__(256, 2) wkv_main(
    const float* __restrict__ r, const float* __restrict__ w,
    const float* __restrict__ k, const float* __restrict__ v,
    const float* __restrict__ init_state, float* __restrict__ state_out)
{
    __shared__ __align__(16) float stage[NSTG][STEPS][STEP_F];
    __shared__ float part[2][32 * PPITCH];   // [parity][col*65 + rg*8 + st]

    const int tid  = threadIdx.x;
    const int bx   = blockIdx.x;   // 0..15 col block
    const int by   = blockIdx.y;   // 0..15 row block
    const int wid  = tid >> 5;     // warp id (0..7) -> col group
    const int lane = tid & 31;
    const int c    = lane & 3;     // col within warp group
    const int rg   = lane >> 2;    // row group (0..7), 4 rows each
    const int col32 = wid * 4 + c;           // col within CTA tile
    const int b    = bx * 32 + col32;        // global column
    const int a0   = by * TILE_R + rg * 4;   // first global row

    // ---- cp.async roles: every thread loads ONE 16B piece for ONE step.
    // tid = sgrp*32 + role; sgrp = step within block (0..7), role = 0..31.
    const int sgrp = tid >> 5;
    const int role = tid & 31;
    const float* basep; int off;
    if (role < 24) {
        const int vec = role >> 3;                    // 0=r 1=w 2=k
        basep = ((vec == 0) ? r : (vec == 1) ? w : k) + by * TILE_R + (role & 7) * 4;
        off = vec * 32 + (role & 7) * 4;
    } else {
        const int q = role - 24;
        basep = v + bx * 32 + q * 4;
        off = 96 + q * 4;
    }
    const float* pA = basep + (size_t)sgrp * DD;
    const unsigned st0 = (unsigned)__cvta_generic_to_shared(&stage[0][0][0]);
    const unsigned offA = st0 + (unsigned)(sgrp * STEP_F + off) * 4u;

    // ---- init state: state0[a][b] = init_state[b]
    const float is0 = init_state[b];
    ull s2[2];
    {
        ull iv = pk2(is0, is0);
        s2[0] = iv; s2[1] = iv;
    }

    // ---- prologue: stage blocks 0 and 1
    CP16(offA, pA);                     CP_COMMIT();
    CP16(offA + STAGE_B, pA + STEPS * DD); CP_COMMIT();
    pA += 2 * STEPS * DD;
    CP_WAIT1();
    __syncthreads();

    // writer base: part[p] + col32*65 + rg*8 ; reader: (st=wid, col=lane)
    const int wbase = col32 * PPITCH + rg * 8;
    const int rbase = lane * PPITCH + wid;
    float* gpr = g_part + (size_t)by * TT * DD + (size_t)bx * 32 + lane;
    const int vidx = 96 + col32;

    int gOff  = 0;                 // byte offset of compute buffer
    unsigned giOff = 2 * STAGE_B;  // byte offset of next issue buffer

    for (int blk = 0; blk < NBLK; blk++) {
        const int p = blk & 1;
        const char* sgb = (const char*)stage + gOff;
        float vals[STEPS];

#pragma unroll
        for (int st = 0; st < STEPS; st++) {
            const ull* sb = (const ull*)(sgb + st * (STEP_F * 4));

            ulonglong2 ra = *reinterpret_cast<const ulonglong2*>(sb + rg * 2);
            ulonglong2 wa = *reinterpret_cast<const ulonglong2*>(sb + 16 + rg * 2);
            ulonglong2 ka = *reinterpret_cast<const ulonglong2*>(sb + 32 + rg * 2);
            const float vf = ((const float*)sb)[vidx];
            const ull vv = pk2(vf, vf);

            // y partial = sum over this thread's 4 rows of r[a]*state[a][b]
            ull p2;
            p2 = f2mul(ra.x, s2[0]);
            p2 = f2fma(ra.y, s2[1], p2);

            // state update: s = w*s + k*v
            s2[0] = f2fma(wa.x, s2[0], f2mul(ka.x, vv));
            s2[1] = f2fma(wa.y, s2[1], f2mul(ka.y, vv));

            float pl, ph; up2(p2, pl, ph);
            vals[st] = pl + ph;
        }

        // batched partial write: 8 STS.32, conflict-free (pitch 65)
        {
            float* pw = &part[p][wbase];
#pragma unroll
            for (int st = 0; st < STEPS; st++) pw[st] = vals[st];
        }

        // stage block blk+2 (1 CP16 per thread)
        if ((blk + 2) < NBLK) CP16(offA + giOff, pA);
        pA += STEPS * DD;
        CP_COMMIT();
        CP_WAIT1();
        __syncthreads();

        // batched reduction: thread (st=wid, col=lane) sums 8 row-group
        // partials; conflict-free reads, coalesced 128B g_part store.
        {
            const float* pr = &part[p][rbase];
            float acc = pr[0];
#pragma unroll
            for (int g = 1; g < 8; g++) acc += pr[g * 8];
            gpr[(size_t)(blk * STEPS + wid) * DD] = acc;
        }

        gOff  = (gOff  == (NSTG - 1) * STAGE_B) ? 0 : gOff  + STAGE_B;
        giOff = (giOff == (NSTG - 1) * STAGE_B) ? 0 : giOff + STAGE_B;
    }

    // ---- final state write (4 rows x 1 col per thread)
    if (state_out) {
#pragma unroll
        for (int i = 0; i < 2; i++) {
            float lo, hi; up2(s2[i], lo, hi);
            state_out[(size_t)(a0 + 2 * i)     * DD + b] = lo;
            state_out[(size_t)(a0 + 2 * i + 1) * DD + b] = hi;
        }
    }
}

// ---------------------------------------------------------------------------
// Combine: y[t][b] = (sum_a r*u*k)*v[t][b] + sum of 16 row-block partials.
// float2-vectorized: 256 threads cover 512 cols as 256 float2s.
// ---------------------------------------------------------------------------
__global__ void __launch_bounds__(256) wkv_combine(
    const float* __restrict__ r, const float* __restrict__ k,
    const float* __restrict__ u, const float* __restrict__ v,
    float* __restrict__ y)
{
    const int t = blockIdx.x;
    const int tid = threadIdx.x;
    __shared__ float red[8];

    const float* rt = r + (size_t)t * DD;
    const float* kt = k + (size_t)t * DD;

    float p = rt[tid] * u[tid] * kt[tid]
            + rt[tid + 256] * u[tid + 256] * kt[tid + 256];
#pragma unroll
    for (int m = 16; m >= 1; m >>= 1) p += __shfl_xor_sync(0xffffffffu, p, m);
    if ((tid & 31) == 0) red[tid >> 5] = p;
    __syncthreads();

    float ruk = 0.f;
#pragma unroll
    for (int g = 0; g < 8; g++) ruk += red[g];

    const float2* v2 = (const float2*)(v + (size_t)t * DD);
    float2* y2 = (float2*)(y + (size_t)t * DD);
    float2 vv = v2[tid];
    float2 acc; acc.x = ruk * vv.x; acc.y = ruk * vv.y;
#pragma unroll
    for (int g = 0; g < NRB; g++) {
        const float2* gp2 = (const float2*)(g_part + (size_t)g * TT * DD + (size_t)t * DD);
        float2 pv = gp2[tid];
        acc.x += pv.x; acc.y += pv.y;
    }
    y2[tid] = acc;
}

// ---------------------------------------------------------------------------
extern "C" void kernel_launch(void* const* d_in, const int* in_sizes, int n_in,
                              void* d_out, int out_size) {
    const float* r          = (const float*)d_in[0];
    const float* w          = (const float*)d_in[1];
    const float* k          = (const float*)d_in[2];
    const float* v          = (const float*)d_in[3];
    const float* init_state = (const float*)d_in[4];
    const float* u          = (const float*)d_in[5];
    float* out = (float*)d_out;

    const int NTD = TT * DD;   // 1048576
    const int NDD = DD * DD;   // 262144

    float* y  = nullptr;
    float* st = nullptr;
    if (out_size >= NTD) {
        y = out;
        if (out_size >= NTD + NDD) st = out + NTD;
    } else if (out_size == NDD) {
        st = out;
    }

    wkv_main<<<dim3(16, 16), 256>>>(r, w, k, v, init_state, st);
    if (y) wkv_combine<<<TT, 256>>>(r, k, u, v, y);
}

// round 7
// speedup vs baseline: 1.4229x; 1.4229x over previous
#include <cuda_runtime.h>
#include <cstdint>

#define TT 2048
#define DD 512
#define STEPS 16
#define NBLK (TT / STEPS)         // 128
#define NSTG 4
#define STEP_F 224                // floats per step staged: r64 w64 k64 v32
#define STAGE_F (STEPS * STEP_F)  // 3584 floats per stage buffer
#define STAGE_B (STAGE_F * 4)     // 14336 bytes
#define PART_F (STEPS * 8 * 36)   // 4608 floats per parity buffer
#define SMEM_FLOATS (NSTG * STAGE_F + 2 * PART_F)   // 23552 floats = 92 KB

// 8 row-blocks of partial y sums, [8][T][D] = 32 MB scratch (deterministic)
__device__ float g_part[(size_t)8 * TT * DD];

typedef unsigned long long ull;

__device__ __forceinline__ ull pk2(float lo, float hi) {
    ull r; asm("mov.b64 %0,{%1,%2};" : "=l"(r) : "f"(lo), "f"(hi)); return r;
}
__device__ __forceinline__ void up2(ull x, float& lo, float& hi) {
    asm("mov.b64 {%0,%1},%2;" : "=f"(lo), "=f"(hi) : "l"(x));
}
__device__ __forceinline__ ull f2fma(ull a, ull b, ull c) {
    ull d; asm("fma.rn.f32x2 %0,%1,%2,%3;" : "=l"(d) : "l"(a), "l"(b), "l"(c)); return d;
}
__device__ __forceinline__ ull f2mul(ull a, ull b) {
    ull d; asm("mul.rn.f32x2 %0,%1,%2;" : "=l"(d) : "l"(a), "l"(b)); return d;
}

#define CP16(dst, src) asm volatile("cp.async.cg.shared.global [%0], [%1], 16;\n" :: "r"(dst), "l"(src))
#define CP_COMMIT()    asm volatile("cp.async.commit_group;\n")
#define CP_WAIT2()     asm volatile("cp.async.wait_group 2;\n" ::: "memory")

// role -> (gmem base pointer, float offset within one step's stage slot)
__device__ __forceinline__ void cp_role(
    int piece, const float* r, const float* w, const float* k, const float* v,
    int bx, int by, const float*& src, unsigned& foff)
{
    const int stp  = piece / 56;          // step within block (0..15)
    const int role = piece - stp * 56;    // 0..55
    const float* basep; int off;
    if (role < 48) {
        const int vec = role >> 4;        // 0=r 1=w 2=k
        basep = ((vec == 0) ? r : (vec == 1) ? w : k) + by * 64 + (role & 15) * 4;
        off = vec * 64 + (role & 15) * 4;
    } else {
        const int q = role - 48;
        basep = v + bx * 32 + q * 4;
        off = 96 + q * 4 + 96;            // v at float offset 192
    }
    src  = basep + (size_t)stp * DD;
    foff = (unsigned)(stp * STEP_F + off);
}

// ---------------------------------------------------------------------------
// Main recurrence kernel. Grid (16 col-blocks, 8 row-blocks), 256 threads,
// 1 CTA/SM. CTA tile 64 rows x 32 cols; warp wid owns cols [wid*4,wid*4+4),
// lane = rg*4 + c; thread = 8 rows x 1 col as 4 f32x2 pairs.
// 16 steps per block: ONE barrier + ONE cp wait + ONE batched reduction.
// 4-deep cp.async stage ring (wait_group 2 => 2 blocks of slack).
// ---------------------------------------------------------------------------
__global__ void __launch_bounds__(256, 1) wkv_main(
    const float* __restrict__ r, const float* __restrict__ w,
    const float* __restrict__ k, const float* __restrict__ v,
    const float* __restrict__ init_state, float* __restrict__ state_out)
{
    extern __shared__ __align__(16) float smem[];
    float* stage = smem;                       // [NSTG][STAGE_F]
    float* partb = smem + NSTG * STAGE_F;      // [2][PART_F], layout [st][rg][36]

    const int tid  = threadIdx.x;
    const int bx   = blockIdx.x;
    const int by   = blockIdx.y;
    const int wid  = tid >> 5;
    const int lane = tid & 31;
    const int c    = lane & 3;
    const int rg   = lane >> 2;
    const int col32 = wid * 4 + c;
    const int b    = bx * 32 + col32;
    const int a0   = by * 64 + rg * 8;

    const unsigned smem_u32 = (unsigned)__cvta_generic_to_shared(smem);

    // ---- cp.async roles: 896 16B pieces per block; thread owns 3 or 4
    const bool has4 = (tid < 128);
    const float *s0, *s1, *s2p, *s3;
    unsigned o0, o1, o2, o3;
    cp_role(tid,        r, w, k, v, bx, by, s0, o0);
    cp_role(tid + 256,  r, w, k, v, bx, by, s1, o1);
    cp_role(tid + 512,  r, w, k, v, bx, by, s2p, o2);
    cp_role(has4 ? tid + 768 : tid, r, w, k, v, bx, by, s3, o3);
    o0 = smem_u32 + o0 * 4u; o1 = smem_u32 + o1 * 4u;
    o2 = smem_u32 + o2 * 4u; o3 = smem_u32 + o3 * 4u;

    // ---- init state
    const float is0 = init_state[b];
    ull s2[4];
    {
        ull iv = pk2(is0, is0);
#pragma unroll
        for (int i = 0; i < 4; i++) s2[i] = iv;
    }

    // ---- prologue: stage blocks 0,1,2
#pragma unroll
    for (int s = 0; s < 3; s++) {
        const size_t adv = (size_t)s * STEPS * DD;
        const unsigned bo = s * STAGE_B;
        CP16(o0 + bo, s0 + adv);
        CP16(o1 + bo, s1 + adv);
        CP16(o2 + bo, s2p + adv);
        if (has4) CP16(o3 + bo, s3 + adv);
        CP_COMMIT();
    }
    s0 += (size_t)3 * STEPS * DD; s1 += (size_t)3 * STEPS * DD;
    s2p += (size_t)3 * STEPS * DD; s3 += (size_t)3 * STEPS * DD;
    CP_WAIT2();
    __syncthreads();

    // reduction roles
    const int wbase = rg * 36 + col32;          // writer: + st*288
    float* gpr = g_part + (size_t)by * TT * DD + (size_t)bx * 32 + lane;
    const int vidx = 192 + col32;

    int gOff  = 0;                  // byte offset of compute buffer
    unsigned giOff = 3 * STAGE_B;   // byte offset of next issue buffer

    for (int blk = 0; blk < NBLK; blk++) {
        const int p = blk & 1;
        const char* sgb = (const char*)stage + gOff;
        float* pp = partb + p * PART_F;
        float vals[STEPS];

#pragma unroll
        for (int st = 0; st < STEPS; st++) {
            const ull* sb = (const ull*)(sgb + st * (STEP_F * 4));

            ulonglong2 ra = *reinterpret_cast<const ulonglong2*>(sb + rg * 4);
            ulonglong2 rb = *reinterpret_cast<const ulonglong2*>(sb + rg * 4 + 2);
            ulonglong2 wa = *reinterpret_cast<const ulonglong2*>(sb + 32 + rg * 4);
            ulonglong2 wb = *reinterpret_cast<const ulonglong2*>(sb + 32 + rg * 4 + 2);
            ulonglong2 ka = *reinterpret_cast<const ulonglong2*>(sb + 64 + rg * 4);
            ulonglong2 kb = *reinterpret_cast<const ulonglong2*>(sb + 64 + rg * 4 + 2);
            const float vf = ((const float*)sb)[vidx];
            const ull vv = pk2(vf, vf);

            ull p2;
            p2 = f2mul(ra.x, s2[0]);
            p2 = f2fma(ra.y, s2[1], p2);
            p2 = f2fma(rb.x, s2[2], p2);
            p2 = f2fma(rb.y, s2[3], p2);

            s2[0] = f2fma(wa.x, s2[0], f2mul(ka.x, vv));
            s2[1] = f2fma(wa.y, s2[1], f2mul(ka.y, vv));
            s2[2] = f2fma(wb.x, s2[2], f2mul(kb.x, vv));
            s2[3] = f2fma(wb.y, s2[3], f2mul(kb.y, vv));

            float pl, ph; up2(p2, pl, ph);
            vals[st] = pl + ph;
        }

        // batched partial write: 16 STS.32, conflict-free ((4rg+4wid+c)%32 distinct)
#pragma unroll
        for (int st = 0; st < STEPS; st++) pp[wbase + st * 288] = vals[st];

        // stage block blk+3
        if (blk + 3 < NBLK) {
            CP16(o0 + giOff, s0);
            CP16(o1 + giOff, s1);
            CP16(o2 + giOff, s2p);
            if (has4) CP16(o3 + giOff, s3);
        }
        s0 += STEPS * DD; s1 += STEPS * DD; s2p += STEPS * DD; s3 += STEPS * DD;
        CP_COMMIT();
        CP_WAIT2();
        __syncthreads();

        // batched reduction: thread handles (col=lane, st=wid) and (col=lane, st=wid+8)
        {
            const size_t t0 = (size_t)blk * STEPS;
#pragma unroll
            for (int h = 0; h < 2; h++) {
                const int st = wid + h * 8;
                const float* pr = pp + st * 288 + lane;
                float acc = pr[0];
#pragma unroll
                for (int g = 1; g < 8; g++) acc += pr[g * 36];
                gpr[(t0 + st) * DD] = acc;
            }
        }

        gOff  = (gOff  == (NSTG - 1) * STAGE_B) ? 0 : gOff  + STAGE_B;
        giOff = (giOff == (NSTG - 1) * STAGE_B) ? 0 : giOff + STAGE_B;
    }

    // ---- final state write
    if (state_out) {
#pragma unroll
        for (int i = 0; i < 4; i++) {
            float lo, hi; up2(s2[i], lo, hi);
            state_out[(size_t)(a0 + 2 * i)     * DD + b] = lo;
            state_out[(size_t)(a0 + 2 * i + 1) * DD + b] = hi;
        }
    }
}

// ---------------------------------------------------------------------------
// Combine: y[t][b] = (sum_a r*u*k)*v[t][b] + sum of 8 row-block partials.
// ---------------------------------------------------------------------------
__global__ void __launch_bounds__(256) wkv_combine(
    const float* __restrict__ r, const float* __restrict__ k,
    const float* __restrict__ u, const float* __restrict__ v,
    float* __restrict__ y)
{
    const int t = blockIdx.x;
    const int tid = threadIdx.x;
    __shared__ float red[8];

    const float* rt = r + (size_t)t * DD;
    const float* kt = k + (size_t)t * DD;

    float p = rt[tid] * u[tid] * kt[tid]
            + rt[tid + 256] * u[tid + 256] * kt[tid + 256];
#pragma unroll
    for (int m = 16; m >= 1; m >>= 1) p += __shfl_xor_sync(0xffffffffu, p, m);
    if ((tid & 31) == 0) red[tid >> 5] = p;
    __syncthreads();

    float ruk = 0.f;
#pragma unroll
    for (int g = 0; g < 8; g++) ruk += red[g];

    const float2* v2 = (const float2*)(v + (size_t)t * DD);
    float2* y2 = (float2*)(y + (size_t)t * DD);
    float2 vv = v2[tid];
    float2 acc; acc.x = ruk * vv.x; acc.y = ruk * vv.y;
#pragma unroll
    for (int g = 0; g < 8; g++) {
        const float2* gp2 = (const float2*)(g_part + (size_t)g * TT * DD + (size_t)t * DD);
        float2 pv = gp2[tid];
        acc.x += pv.x; acc.y += pv.y;
    }
    y2[tid] = acc;
}

// ---------------------------------------------------------------------------
extern "C" void kernel_launch(void* const* d_in, const int* in_sizes, int n_in,
                              void* d_out, int out_size) {
    const float* r          = (const float*)d_in[0];
    const float* w          = (const float*)d_in[1];
    const float* k          = (const float*)d_in[2];
    const float* v          = (const float*)d_in[3];
    const float* init_state = (const float*)d_in[4];
    const float* u          = (const float*)d_in[5];
    float* out = (float*)d_out;

    const int NTD = TT * DD;   // 1048576
    const int NDD = DD * DD;   // 262144

    float* y  = nullptr;
    float* st = nullptr;
    if (out_size >= NTD) {
        y = out;
        if (out_size >= NTD + NDD) st = out + NTD;
    } else if (out_size == NDD) {
        st = out;
    }

    const int smem_bytes = SMEM_FLOATS * 4;    // 94208
    static bool attr_set = false;
    if (!attr_set) {
        cudaFuncSetAttribute(wkv_main, cudaFuncAttributeMaxDynamicSharedMemorySize, smem_bytes);
        attr_set = true;
    }

    wkv_main<<<dim3(16, 8), 256, smem_bytes>>>(r, w, k, v, init_state, st);
    if (y) wkv_combine<<<TT, 256>>>(r, k, u, v, y);
}